// round 3
// baseline (speedup 1.0000x reference)
#include <cuda_runtime.h>
#include <cuda_fp16.h>
#include <stdint.h>

// ---------------------------------------------------------------------------
// SplitNN forward, two-phase:
//  K1: out1 = x1@W1+b1 (fp16 mma, fp32 acc) -> fp16 scratch (coalesced STG.128
//      via smem staging); per-block min/max of row L1 norms -> g_bmin/g_bmax.
//  K2: out2 = x2@W2+b2; cp.async-prefetch noise + out1 tiles overlapping mma;
//      linear epilogue: min((out1+noise*mul)*mask, out2) @ Ws + bs.
// ---------------------------------------------------------------------------

#define BROWS   262144
#define FDIM    160
#define HDIM    128
#define CDIM    10
#define TILE_M  128
#define NTHREADS 256
#define NBLOCKS (BROWS / TILE_M)   // 2048

#define LDA 168           // halfs per x-row in smem (160 + 8 pad)
#define LDW 136           // halfs per W-row in smem (128 + 8 pad)
#define LDO 136           // halfs per out1-stage row (272B = 17*16B)
#define LDN 136           // floats per noise row (544B = 34*16B)
#define A_BYTES (TILE_M * LDA * 2)       // 43008
#define W_BYTES (FDIM * LDW * 2)         // 43520
#define O_BYTES (TILE_M * LDO * 2)       // 34816
#define N_BYTES (TILE_M * LDN * 4)       // 69632
#define K1_SMEM (A_BYTES + W_BYTES)                      // 86528
#define K2_SMEM (A_BYTES + W_BYTES + N_BYTES + O_BYTES)  // 190976

// fp16 scratch for gemm1+b1 (allocation-free: __device__ global).
// __align__(128): required for STG.128 / cp.async 16B access paths.
__device__ __align__(128) __half g_out1[(size_t)BROWS * HDIM];
__device__ float g_bmin[NBLOCKS];
__device__ float g_bmax[NBLOCKS];

__device__ __forceinline__ uint32_t su32(const void* p) {
    return (uint32_t)__cvta_generic_to_shared(p);
}
__device__ __forceinline__ void ldsm4(uint32_t* r, uint32_t a) {
    asm volatile("ldmatrix.sync.aligned.m8n8.x4.shared.b16 {%0,%1,%2,%3},[%4];"
                 : "=r"(r[0]), "=r"(r[1]), "=r"(r[2]), "=r"(r[3]) : "r"(a));
}
__device__ __forceinline__ void ldsm4t(uint32_t* r, uint32_t a) {
    asm volatile("ldmatrix.sync.aligned.m8n8.x4.trans.shared.b16 {%0,%1,%2,%3},[%4];"
                 : "=r"(r[0]), "=r"(r[1]), "=r"(r[2]), "=r"(r[3]) : "r"(a));
}
__device__ __forceinline__ void mma16816(float* c, const uint32_t* a, const uint32_t* b) {
    asm volatile("mma.sync.aligned.m16n8k16.row.col.f32.f16.f16.f32 "
                 "{%0,%1,%2,%3},{%4,%5,%6,%7},{%8,%9},{%0,%1,%2,%3};"
                 : "+f"(c[0]), "+f"(c[1]), "+f"(c[2]), "+f"(c[3])
                 : "r"(a[0]), "r"(a[1]), "r"(a[2]), "r"(a[3]), "r"(b[0]), "r"(b[1]));
}
__device__ __forceinline__ void cpasync16(void* sdst, const void* gsrc) {
    asm volatile("cp.async.cg.shared.global [%0],[%1],16;"
                 :: "r"(su32(sdst)), "l"(gsrc));
}
__device__ __forceinline__ void cpasync_commit() {
    asm volatile("cp.async.commit_group;");
}
__device__ __forceinline__ void cpasync_wait0() {
    asm volatile("cp.async.wait_group 0;" ::: "memory");
}

// Load x tile [128][160] fp32 -> fp16 smem, and W [160][128] fp32 -> fp16 smem.
__device__ __forceinline__ void load_tiles(const float* __restrict__ x,
                                           const float* __restrict__ W,
                                           __half* sA, __half* sW,
                                           size_t row0, int tid) {
    const float4* xs = reinterpret_cast<const float4*>(x) + row0 * (FDIM / 4);
    #pragma unroll
    for (int i = tid; i < TILE_M * (FDIM / 4); i += NTHREADS) {
        int r = i / (FDIM / 4), c = i % (FDIM / 4);
        float4 v = xs[i];
        *reinterpret_cast<__half2*>(&sA[r * LDA + c * 4])     = __floats2half2_rn(v.x, v.y);
        *reinterpret_cast<__half2*>(&sA[r * LDA + c * 4 + 2]) = __floats2half2_rn(v.z, v.w);
    }
    const float4* ws = reinterpret_cast<const float4*>(W);
    #pragma unroll
    for (int i = tid; i < FDIM * (HDIM / 4); i += NTHREADS) {
        int r = i / (HDIM / 4), c = i % (HDIM / 4);
        float4 v = ws[i];
        *reinterpret_cast<__half2*>(&sW[r * LDW + c * 4])     = __floats2half2_rn(v.x, v.y);
        *reinterpret_cast<__half2*>(&sW[r * LDW + c * 4 + 2]) = __floats2half2_rn(v.z, v.w);
    }
}

// Full K=160 mainloop: acc[mt][nt][4] += A(warp rows) * W
__device__ __forceinline__ void mma_tile(const __half* sA, const __half* sW,
                                         float acc[2][8][4], int lane, int wm, int wn) {
    uint32_t aBase = su32(sA), wBase = su32(sW);
    int lr = lane & 15, lc = lane >> 4;
    #pragma unroll
    for (int kk = 0; kk < FDIM / 16; kk++) {
        uint32_t afr[2][4], bfr[4][4];
        #pragma unroll
        for (int mt = 0; mt < 2; mt++)
            ldsm4(afr[mt], aBase + (uint32_t)(((wm * 32 + mt * 16 + lr) * LDA + kk * 16 + lc * 8) * 2));
        #pragma unroll
        for (int nt2 = 0; nt2 < 4; nt2++)
            ldsm4t(bfr[nt2], wBase + (uint32_t)(((kk * 16 + lr) * LDW + wn * 64 + nt2 * 16 + lc * 8) * 2));
        #pragma unroll
        for (int mt = 0; mt < 2; mt++)
            #pragma unroll
            for (int nt = 0; nt < 8; nt++)
                mma16816(acc[mt][nt], afr[mt], &bfr[nt >> 1][(nt & 1) * 2]);
    }
}

// ---------------- Kernel 1: gemm1 + bias, L1-norm min/max, fp16 scratch -----
__global__ __launch_bounds__(NTHREADS, 2)
void k1_kernel(const float* __restrict__ x1, const float* __restrict__ W1,
               const float* __restrict__ b1) {
    extern __shared__ __align__(16) char dyn[];
    __half* sA = (__half*)dyn;
    __half* sW = (__half*)(dyn + A_BYTES);
    __half* stage = (__half*)dyn;              // alias after mma (34816 < 86528)
    __shared__ float sB1[HDIM];
    __shared__ float sNormP[HDIM][2];
    __shared__ float sRed[4][2];

    int tid = threadIdx.x, lane = tid & 31, warp = tid >> 5;
    int wm = warp >> 1, wn = warp & 1;
    size_t row0 = (size_t)blockIdx.x * TILE_M;

    load_tiles(x1, W1, sA, sW, row0, tid);
    if (tid < HDIM) sB1[tid] = b1[tid];
    __syncthreads();

    float acc[2][8][4];
    #pragma unroll
    for (int a = 0; a < 2; a++)
        #pragma unroll
        for (int b = 0; b < 8; b++)
            #pragma unroll
            for (int c = 0; c < 4; c++) acc[a][b][c] = 0.f;

    mma_tile(sA, sW, acc, lane, wm, wn);
    __syncthreads();   // all warps done reading sA/sW before aliasing as stage

    int qr = lane >> 2, qc = lane & 3;
    #pragma unroll
    for (int mt = 0; mt < 2; mt++) {
        int rl = wm * 32 + mt * 16 + qr;
        float pLo = 0.f, pHi = 0.f;
        #pragma unroll
        for (int nt = 0; nt < 8; nt++) {
            int col = wn * 64 + nt * 8 + qc * 2;
            float* c = acc[mt][nt];
            float v0 = c[0] + sB1[col], v1 = c[1] + sB1[col + 1];
            float v2 = c[2] + sB1[col], v3 = c[3] + sB1[col + 1];
            *reinterpret_cast<__half2*>(&stage[rl * LDO + col])       = __floats2half2_rn(v0, v1);
            *reinterpret_cast<__half2*>(&stage[(rl + 8) * LDO + col]) = __floats2half2_rn(v2, v3);
            pLo += fabsf(v0) + fabsf(v1);
            pHi += fabsf(v2) + fabsf(v3);
        }
        pLo += __shfl_xor_sync(0xffffffffu, pLo, 1);
        pLo += __shfl_xor_sync(0xffffffffu, pLo, 2);
        pHi += __shfl_xor_sync(0xffffffffu, pHi, 1);
        pHi += __shfl_xor_sync(0xffffffffu, pHi, 2);
        if (qc == 0) { sNormP[rl][wn] = pLo; sNormP[rl + 8][wn] = pHi; }
    }
    __syncthreads();

    // Coalesced STG.128 of the staged fp16 tile: 2048 uint4, 8 per thread.
    const uint4* s4 = reinterpret_cast<const uint4*>(dyn);
    uint4* g4 = reinterpret_cast<uint4*>(g_out1 + row0 * HDIM);
    #pragma unroll
    for (int t = 0; t < 8; t++) {
        int i = tid + t * NTHREADS;
        int r = i >> 4, c = i & 15;
        g4[i] = s4[r * (LDO / 8) + c];     // LDO/8 = 17 uint4 per row
    }

    // Block min/max of row L1 norms -> per-block arrays (no atomics, no init).
    if (tid < HDIM) {
        float v = sNormP[tid][0] + sNormP[tid][1];
        float mn = v, mx = v;
        #pragma unroll
        for (int o = 16; o; o >>= 1) {
            mn = fminf(mn, __shfl_xor_sync(0xffffffffu, mn, o));
            mx = fmaxf(mx, __shfl_xor_sync(0xffffffffu, mx, o));
        }
        if (lane == 0) { sRed[warp][0] = mn; sRed[warp][1] = mx; }
    }
    __syncthreads();
    if (tid == 0) {
        g_bmin[blockIdx.x] = fminf(fminf(sRed[0][0], sRed[1][0]), fminf(sRed[2][0], sRed[3][0]));
        g_bmax[blockIdx.x] = fmaxf(fmaxf(sRed[0][1], sRed[1][1]), fmaxf(sRed[2][1], sRed[3][1]));
    }
}

// ---------------- Kernel 2: gemm2, noise+mask+min, projection to 10 ---------
__global__ __launch_bounds__(NTHREADS, 1)
void k2_kernel(const float* __restrict__ x2, const float* __restrict__ W2,
               const float* __restrict__ b2, const float* __restrict__ Ws,
               const float* __restrict__ bs, const float* __restrict__ noise,
               const float* __restrict__ rr, float* __restrict__ out) {
    extern __shared__ __align__(16) char dyn[];
    __half* sA = (__half*)dyn;
    __half* sW = (__half*)(dyn + A_BYTES);
    float*  sNoise = (float*)(dyn + A_BYTES + W_BYTES);
    __half* sOut1  = (__half*)(dyn + A_BYTES + W_BYTES + N_BYTES);
    float*  sServ  = (float*)dyn;              // alias after mma (69632 < 86528)
    __shared__ float sB2[HDIM];
    __shared__ float sMask[HDIM];
    __shared__ float sWs[HDIM * 12];           // 10 cols padded to 12 (zero pad)
    __shared__ float sBs[CDIM];
    __shared__ float sRed[8][2];
    __shared__ float sMul;

    int tid = threadIdx.x, lane = tid & 31, warp = tid >> 5;
    int wm = warp >> 1, wn = warp & 1;
    size_t row0 = (size_t)blockIdx.x * TILE_M;

    load_tiles(x2, W2, sA, sW, row0, tid);

    // Prefetch noise [128][128] fp32 and out1 [128][128] fp16 tiles via cp.async;
    // they transfer while the mma mainloop runs.
    {
        const char* nsrc = (const char*)(noise + row0 * HDIM);
        char* ndst = (char*)sNoise;
        #pragma unroll
        for (int t = 0; t < 16; t++) {
            int i = tid + t * NTHREADS;          // 4096 x 16B
            int r = i >> 5, c = i & 31;
            cpasync16(ndst + r * (LDN * 4) + c * 16, nsrc + (size_t)r * 512 + c * 16);
        }
        const char* osrc = (const char*)(g_out1 + row0 * HDIM);
        char* odst = (char*)sOut1;
        #pragma unroll
        for (int t = 0; t < 8; t++) {
            int i = tid + t * NTHREADS;          // 2048 x 16B
            int r = i >> 4, c = i & 15;
            cpasync16(odst + r * (LDO * 2) + c * 16, osrc + (size_t)r * 256 + c * 16);
        }
        cpasync_commit();
    }

    if (tid < HDIM) {
        sB2[tid] = b2[tid];
        sMask[tid] = (rr[tid] < 0.95f) ? 1.f : 0.f;
    }
    #pragma unroll
    for (int i = tid; i < HDIM * 12; i += NTHREADS) {
        int r = i / 12, c = i % 12;
        sWs[i] = (c < CDIM) ? Ws[r * CDIM + c] : 0.f;
    }
    if (tid < CDIM) sBs[tid] = bs[tid];

    // Global sensitivity: reduce per-block min/max arrays (2048 each, L2 hits).
    {
        float mn = __int_as_float(0x7f800000), mx = 0.f;
        #pragma unroll
        for (int j = tid; j < NBLOCKS; j += NTHREADS) {
            mn = fminf(mn, g_bmin[j]);
            mx = fmaxf(mx, g_bmax[j]);
        }
        #pragma unroll
        for (int o = 16; o; o >>= 1) {
            mn = fminf(mn, __shfl_xor_sync(0xffffffffu, mn, o));
            mx = fmaxf(mx, __shfl_xor_sync(0xffffffffu, mx, o));
        }
        if (lane == 0) { sRed[warp][0] = mn; sRed[warp][1] = mx; }
    }
    __syncthreads();
    if (tid == 0) {
        float mn = sRed[0][0], mx = sRed[0][1];
        #pragma unroll
        for (int w = 1; w < 8; w++) {
            mn = fminf(mn, sRed[w][0]);
            mx = fmaxf(mx, sRed[w][1]);
        }
        sMul = (mx - mn) * 7.5f;   // sensitivity / EPS, EPS = 4/30
    }

    float acc[2][8][4];
    #pragma unroll
    for (int a = 0; a < 2; a++)
        #pragma unroll
        for (int b = 0; b < 8; b++)
            #pragma unroll
            for (int c = 0; c < 4; c++) acc[a][b][c] = 0.f;

    mma_tile(sA, sW, acc, lane, wm, wn);
    __syncthreads();   // all warps done reading sA/sW before aliasing as sServ

    // Epilogue A: out2 = acc + b2 -> sServ (fp32, fragment -> linear layout)
    int qr = lane >> 2, qc = lane & 3;
    #pragma unroll
    for (int mt = 0; mt < 2; mt++) {
        int rl = wm * 32 + mt * 16 + qr;
        #pragma unroll
        for (int nt = 0; nt < 8; nt++) {
            int col = wn * 64 + nt * 8 + qc * 2;
            float* c = acc[mt][nt];
            *reinterpret_cast<float2*>(&sServ[rl * LDN + col]) =
                make_float2(c[0] + sB2[col], c[1] + sB2[col + 1]);
            *reinterpret_cast<float2*>(&sServ[(rl + 8) * LDN + col]) =
                make_float2(c[2] + sB2[col], c[3] + sB2[col + 1]);
        }
    }
    cpasync_wait0();
    __syncthreads();

    // Epilogue B: linear pass. 2 threads per row, 64 h each.
    int prow = tid >> 1, ph = tid & 1;
    int hoff = ph * 64;
    const float*  nrow = sNoise + prow * LDN + hoff;
    const __half* orow = sOut1 + prow * LDO + hoff;
    const float*  srow = sServ + prow * LDN + hoff;
    float mul = sMul;
    float p[CDIM];
    #pragma unroll
    for (int c = 0; c < CDIM; c++) p[c] = 0.f;
    #pragma unroll
    for (int h = 0; h < 64; h += 2) {
        float2 o1 = __half22float2(*reinterpret_cast<const __half2*>(&orow[h]));
        float2 nz = *reinterpret_cast<const float2*>(&nrow[h]);
        float2 o2 = *reinterpret_cast<const float2*>(&srow[h]);
        float s0 = fminf((o1.x + nz.x * mul) * sMask[hoff + h],     o2.x);
        float s1 = fminf((o1.y + nz.y * mul) * sMask[hoff + h + 1], o2.y);
        const float4* w0 = reinterpret_cast<const float4*>(&sWs[(hoff + h) * 12]);
        float4 a0 = w0[0], a1 = w0[1];
        float2 a2 = reinterpret_cast<const float2*>(w0)[4];
        const float4* w1 = reinterpret_cast<const float4*>(&sWs[(hoff + h + 1) * 12]);
        float4 d0 = w1[0], d1 = w1[1];
        float2 d2 = reinterpret_cast<const float2*>(w1)[4];
        p[0] += s0 * a0.x; p[1] += s0 * a0.y; p[2] += s0 * a0.z; p[3] += s0 * a0.w;
        p[4] += s0 * a1.x; p[5] += s0 * a1.y; p[6] += s0 * a1.z; p[7] += s0 * a1.w;
        p[8] += s0 * a2.x; p[9] += s0 * a2.y;
        p[0] += s1 * d0.x; p[1] += s1 * d0.y; p[2] += s1 * d0.z; p[3] += s1 * d0.w;
        p[4] += s1 * d1.x; p[5] += s1 * d1.y; p[6] += s1 * d1.z; p[7] += s1 * d1.w;
        p[8] += s1 * d2.x; p[9] += s1 * d2.y;
    }
    #pragma unroll
    for (int c = 0; c < CDIM; c++) p[c] += __shfl_xor_sync(0xffffffffu, p[c], 1);
    if (ph == 0) {
        float* o = out + (row0 + prow) * CDIM;
        #pragma unroll
        for (int c = 0; c < CDIM; c++) o[c] = p[c] + sBs[c];
    }
}

// ---------------------------------------------------------------------------
extern "C" void kernel_launch(void* const* d_in, const int* in_sizes, int n_in,
                              void* d_out, int out_size) {
    (void)in_sizes; (void)n_in; (void)out_size;
    const float* x1    = (const float*)d_in[0];
    const float* x2    = (const float*)d_in[1];
    const float* W1    = (const float*)d_in[2];
    const float* b1    = (const float*)d_in[3];
    const float* W2    = (const float*)d_in[4];
    const float* b2    = (const float*)d_in[5];
    const float* Ws    = (const float*)d_in[6];
    const float* bs    = (const float*)d_in[7];
    const float* noise = (const float*)d_in[8];
    const float* rr    = (const float*)d_in[9];
    float* out = (float*)d_out;

    cudaFuncSetAttribute(k1_kernel, cudaFuncAttributeMaxDynamicSharedMemorySize, K1_SMEM);
    cudaFuncSetAttribute(k2_kernel, cudaFuncAttributeMaxDynamicSharedMemorySize, K2_SMEM);

    k1_kernel<<<NBLOCKS, NTHREADS, K1_SMEM>>>(x1, W1, b1);
    k2_kernel<<<NBLOCKS, NTHREADS, K2_SMEM>>>(x2, W2, b2, Ws, bs, noise, rr, out);
}